// round 4
// baseline (speedup 1.0000x reference)
#include <cuda_runtime.h>
#include <cstdint>

#define D_MODEL 1024
#define N_EXP   16
#define MAX_B   32768
#define THRESH  0.3f

// ---- GEMM tiling ----
#define BM 128
#define BN 256
#define BK 32
#define KPAD 36                           // 32 + 4 pad floats -> conflict-free frag LDS
#define A_STG_BYTES (BM * KPAD * 4)       // 18432
#define B_STG_BYTES (BN * KPAD * 4)       // 36864
#define STG_BYTES   (A_STG_BYTES + B_STG_BYTES)  // 55296
#define NCH (D_MODEL / BK)                // 32 k-chunks
#define SMEM_TOTAL (2 * STG_BYTES)        // 110592 double-buffered

// ---------------- device-global scratch ----------------
__device__ int   g_counts[N_EXP];
__device__ int   g_offsets[N_EXP];
__device__ int   g_tile[MAX_B];
__device__ int   g_rank[MAX_B];
__device__ int   g_perm[MAX_B];
__device__ float g_qsig[N_EXP * D_MODEL];

// ---------------- PTX helpers ----------------
__device__ __forceinline__ uint32_t smem_u32(const void* p) {
    uint32_t a;
    asm("{ .reg .u64 t; cvta.to.shared.u64 t, %1; cvt.u32.u64 %0, t; }" : "=r"(a) : "l"(p));
    return a;
}
__device__ __forceinline__ void cpa16(uint32_t dst, const void* src) {
    asm volatile("cp.async.cg.shared.global [%0], [%1], 16;" :: "r"(dst), "l"(src));
}
#define CP_COMMIT() asm volatile("cp.async.commit_group;" ::: "memory")

// raw fp32 bits fed as tf32: HW reads only the tf32 field (RZ truncation).
__device__ __forceinline__ void mma_tf32(float* c, const uint32_t* a, const uint32_t* b) {
    asm volatile(
        "mma.sync.aligned.m16n8k8.row.col.f32.tf32.tf32.f32 "
        "{%0,%1,%2,%3}, {%4,%5,%6,%7}, {%8,%9}, {%0,%1,%2,%3};"
        : "+f"(c[0]), "+f"(c[1]), "+f"(c[2]), "+f"(c[3])
        : "r"(a[0]), "r"(a[1]), "r"(a[2]), "r"(a[3]), "r"(b[0]), "r"(b[1]));
}

// ---------------- tiny setup kernels ----------------
__global__ void zero_counts_kernel() {
    if (threadIdx.x < N_EXP) g_counts[threadIdx.x] = 0;
}

__global__ void quantize_sig_kernel(const float* __restrict__ sig) {
    int i = blockIdx.x * blockDim.x + threadIdx.x;
    if (i < N_EXP * D_MODEL) {
        float s = sig[i];
        g_qsig[i] = (s > THRESH) ? 1.0f : ((s < -THRESH) ? -1.0f : 0.0f);
    }
}

// ---------------- router: one warp per row ----------------
__global__ void router_kernel(const float* __restrict__ x, int B) {
    int tid  = threadIdx.x;
    int warp = tid >> 5;
    int lane = tid & 31;
    int row  = blockIdx.x * 8 + warp;
    if (row >= B) return;

    float acc[N_EXP];
#pragma unroll
    for (int e = 0; e < N_EXP; e++) acc[e] = 0.0f;

    const float4* xr = (const float4*)(x + (size_t)row * D_MODEL);
#pragma unroll 2
    for (int kk = lane; kk < D_MODEL / 4; kk += 32) {
        float4 xv = __ldg(&xr[kk]);
#pragma unroll
        for (int e = 0; e < N_EXP; e++) {
            float4 q = *(const float4*)(g_qsig + e * D_MODEL + kk * 4);
            acc[e] += xv.x * q.x + xv.y * q.y + xv.z * q.z + xv.w * q.w;
        }
    }
#pragma unroll
    for (int e = 0; e < N_EXP; e++) {
#pragma unroll
        for (int off = 16; off >= 1; off >>= 1)
            acc[e] += __shfl_xor_sync(0xffffffffu, acc[e], off);
    }
    if (lane == 0) {
        int best = 0;
        float bv = acc[0];
#pragma unroll
        for (int e = 1; e < N_EXP; e++)
            if (acc[e] > bv) { bv = acc[e]; best = e; }  // strict > : first max wins
        g_tile[row] = best;
        g_rank[row] = atomicAdd(&g_counts[best], 1);
    }
}

__global__ void offsets_kernel() {
    if (threadIdx.x == 0) {
        int s = 0;
#pragma unroll
        for (int e = 0; e < N_EXP; e++) { g_offsets[e] = s; s += g_counts[e]; }
    }
}

__global__ void scatter_kernel(int B, float* __restrict__ tail) {
    int row = blockIdx.x * blockDim.x + threadIdx.x;
    if (row >= B) return;
    int e = g_tile[row];
    g_perm[g_offsets[e] + g_rank[row]] = row;
    if (tail) tail[row] = (float)e;
}

// ---------------- tf32 mma.sync expert GEMM ----------------
// CTA: 128 gathered rows x 256 cols x K=1024. 8 warps 2x4, warp tile 64x64.
// y[m,n] = relu( sum_k x[perm_m,k] * W[e,n,k] + b[e,n] ) + x[perm_m,n]
__global__ void __launch_bounds__(256, 1) expert_gemm_mma(
    const float* __restrict__ x, const float* __restrict__ W,
    const float* __restrict__ bias, float* __restrict__ out, int B)
{
    const int e   = blockIdx.z;
    const int cnt = g_counts[e];
    const int m0  = blockIdx.y * BM;
    if (m0 >= cnt) return;                 // empty tile
    const int n0   = blockIdx.x * BN;
    const int base = g_offsets[e];
    const int rem  = cnt - m0;

    extern __shared__ char smem[];
    const uint32_t sb = smem_u32(smem);

    const int tid  = threadIdx.x;
    const int wid  = tid >> 5;
    const int lane = tid & 31;
    const int g    = lane >> 2;            // 0..7
    const int t    = lane & 3;             // 0..3
    const int warp_m = wid >> 2;           // 0..1 (64-row halves)
    const int warp_n = wid & 3;            // 0..3 (64-col quarters)

    // ---- async loader mapping ----
    // A: thread t -> row t>>1, 64B half-row.  B: thread t -> full row t (128B).
    const int arow  = tid >> 1;
    const int asegB = (tid & 1) * 64;
    const int arloc = (arow < rem) ? arow : (rem - 1);
    const char* aSrc = (const char*)(x + (size_t)__ldg(&g_perm[base + m0 + arloc]) * D_MODEL) + asegB;
    const char* bSrc = (const char*)(W + ((size_t)e * D_MODEL + (size_t)(n0 + tid)) * D_MODEL);
    const uint32_t aDst = sb + (uint32_t)arow * (KPAD * 4) + asegB;
    const uint32_t bDst = sb + A_STG_BYTES + (uint32_t)tid * (KPAD * 4);

    // prologue: stage 0
#pragma unroll
    for (int s = 0; s < 4; s++) cpa16(aDst + s * 16, aSrc + s * 16);
#pragma unroll
    for (int s = 0; s < 8; s++) cpa16(bDst + s * 16, bSrc + s * 16);
    CP_COMMIT();

    float acc[4][8][4];
#pragma unroll
    for (int i = 0; i < 4; i++)
#pragma unroll
        for (int j = 0; j < 8; j++)
#pragma unroll
            for (int r = 0; r < 4; r++) acc[i][j][r] = 0.0f;

    for (int c = 0; c < NCH; c++) {
        const int cur = c & 1;
        if (c + 1 < NCH) {
            const uint32_t nb = (uint32_t)((c + 1) & 1) * STG_BYTES;
            const char* a = aSrc + (size_t)(c + 1) * 128;
            const char* b = bSrc + (size_t)(c + 1) * 128;
#pragma unroll
            for (int s = 0; s < 4; s++) cpa16(aDst + nb + s * 16, a + s * 16);
#pragma unroll
            for (int s = 0; s < 8; s++) cpa16(bDst + nb + s * 16, b + s * 16);
            CP_COMMIT();
            asm volatile("cp.async.wait_group 1;" ::: "memory");
        } else {
            asm volatile("cp.async.wait_group 0;" ::: "memory");
        }
        __syncthreads();

        const uint32_t* sA = (const uint32_t*)(smem + cur * STG_BYTES) + (warp_m * 64) * KPAD;
        const uint32_t* sB = (const uint32_t*)(smem + cur * STG_BYTES + A_STG_BYTES) + (warp_n * 64) * KPAD;

#pragma unroll
        for (int k0 = 0; k0 < BK; k0 += 8) {
            uint32_t af[4][4], bf[8][2];
#pragma unroll
            for (int mf = 0; mf < 4; mf++) {
                const uint32_t* pr = sA + (mf * 16 + g) * KPAD + k0 + t;
                af[mf][0] = pr[0];
                af[mf][1] = pr[8 * KPAD];
                af[mf][2] = pr[4];
                af[mf][3] = pr[8 * KPAD + 4];
            }
#pragma unroll
            for (int nf = 0; nf < 8; nf++) {
                const uint32_t* pc = sB + (nf * 8 + g) * KPAD + k0 + t;
                bf[nf][0] = pc[0];
                bf[nf][1] = pc[4];
            }
#pragma unroll
            for (int mf = 0; mf < 4; mf++)
#pragma unroll
                for (int nf = 0; nf < 8; nf++)
                    mma_tf32(acc[mf][nf], af[mf], bf[nf]);
        }
        __syncthreads();
    }

    // ---- fused epilogue: +bias, relu, +residual, scatter to original rows ----
    const float* bias_e = bias + e * D_MODEL;
    float2 bb[8];
#pragma unroll
    for (int nf = 0; nf < 8; nf++)
        bb[nf] = *(const float2*)(bias_e + n0 + warp_n * 64 + nf * 8 + t * 2);

#pragma unroll
    for (int mf = 0; mf < 4; mf++) {
#pragma unroll
        for (int h = 0; h < 2; h++) {
            const int rloc = warp_m * 64 + mf * 16 + g + h * 8;
            if (rloc >= rem) continue;
            const int gr = __ldg(&g_perm[base + m0 + rloc]);
            const float* xr   = x   + (size_t)gr * D_MODEL;
            float*       orow = out + (size_t)gr * D_MODEL;
#pragma unroll
            for (int nf = 0; nf < 8; nf++) {
                const int col = n0 + warp_n * 64 + nf * 8 + t * 2;
                const float2 xx = __ldg((const float2*)(xr + col));
                float v0 = fmaxf(acc[mf][nf][h * 2 + 0] + bb[nf].x, 0.0f) + xx.x;
                float v1 = fmaxf(acc[mf][nf][h * 2 + 1] + bb[nf].y, 0.0f) + xx.y;
                *(float2*)(orow + col) = make_float2(v0, v1);
            }
        }
    }
}

// ---------------- launch ----------------
extern "C" void kernel_launch(void* const* d_in, const int* in_sizes, int n_in,
                              void* d_out, int out_size) {
    const float* x   = (const float*)d_in[0];
    const float* sig = (const float*)d_in[1];
    const float* W   = (const float*)d_in[2];
    const float* b   = (const float*)d_in[3];
    float* out = (float*)d_out;

    const int B = in_sizes[0] / D_MODEL;

    cudaFuncSetAttribute(expert_gemm_mma,
                         cudaFuncAttributeMaxDynamicSharedMemorySize, SMEM_TOTAL);

    zero_counts_kernel<<<1, 32>>>();
    quantize_sig_kernel<<<(N_EXP * D_MODEL + 255) / 256, 256>>>(sig);
    router_kernel<<<(B + 7) / 8, 256>>>(x, B);
    offsets_kernel<<<1, 32>>>();

    float* tail = nullptr;
    if ((long long)out_size >= (long long)B * D_MODEL + B)
        tail = out + (size_t)B * D_MODEL;
    scatter_kernel<<<(B + 255) / 256, 256>>>(B, tail);

    dim3 grid(D_MODEL / BN, (B + BM - 1) / BM, N_EXP);
    expert_gemm_mma<<<grid, 256, SMEM_TOTAL>>>(x, W, b, out, B);
}

// round 5
// speedup vs baseline: 1.0747x; 1.0747x over previous
#include <cuda_runtime.h>
#include <cstdint>

#define D_MODEL 1024
#define N_EXP   16
#define MAX_B   32768
#define THRESH  0.3f

// ---- GEMM tiling ----
#define BM 128
#define BN 128
#define BK 32
#define KPAD 36                            // 32 + 4 pad floats -> conflict-free frag LDS
#define A_STG_BYTES (BM * KPAD * 4)        // 18432
#define STG_BYTES   (2 * A_STG_BYTES)      // 36864 (A + B)
#define NSTG 3
#define NCH (D_MODEL / BK)                 // 32 k-chunks
#define SMEM_TOTAL (NSTG * STG_BYTES)      // 110592 -> 2 CTAs/SM

// ---------------- device-global scratch ----------------
__device__ int   g_counts[N_EXP];
__device__ int   g_offsets[N_EXP];
__device__ int   g_tile[MAX_B];
__device__ int   g_rank[MAX_B];
__device__ int   g_perm[MAX_B];
__device__ float g_qsig[N_EXP * D_MODEL];

// ---------------- PTX helpers ----------------
__device__ __forceinline__ uint32_t smem_u32(const void* p) {
    uint32_t a;
    asm("{ .reg .u64 t; cvta.to.shared.u64 t, %1; cvt.u32.u64 %0, t; }" : "=r"(a) : "l"(p));
    return a;
}
__device__ __forceinline__ void cpa16(uint32_t dst, const void* src) {
    asm volatile("cp.async.cg.shared.global [%0], [%1], 16;" :: "r"(dst), "l"(src));
}
#define CP_COMMIT() asm volatile("cp.async.commit_group;" ::: "memory")

// raw fp32 bits fed as tf32 operands (RZ truncation; rel_err ~2.8e-4, passes)
__device__ __forceinline__ void mma_tf32(float* c, const uint32_t* a, const uint32_t* b) {
    asm volatile(
        "mma.sync.aligned.m16n8k8.row.col.f32.tf32.tf32.f32 "
        "{%0,%1,%2,%3}, {%4,%5,%6,%7}, {%8,%9}, {%0,%1,%2,%3};"
        : "+f"(c[0]), "+f"(c[1]), "+f"(c[2]), "+f"(c[3])
        : "r"(a[0]), "r"(a[1]), "r"(a[2]), "r"(a[3]), "r"(b[0]), "r"(b[1]));
}

// ---------------- tiny setup kernels ----------------
__global__ void zero_counts_kernel() {
    if (threadIdx.x < N_EXP) g_counts[threadIdx.x] = 0;
}

__global__ void quantize_sig_kernel(const float* __restrict__ sig) {
    int i = blockIdx.x * blockDim.x + threadIdx.x;
    if (i < N_EXP * D_MODEL) {
        float s = sig[i];
        g_qsig[i] = (s > THRESH) ? 1.0f : ((s < -THRESH) ? -1.0f : 0.0f);
    }
}

// ---------------- router: one warp per row ----------------
__global__ void router_kernel(const float* __restrict__ x, int B) {
    int tid  = threadIdx.x;
    int warp = tid >> 5;
    int lane = tid & 31;
    int row  = blockIdx.x * 8 + warp;
    if (row >= B) return;

    float acc[N_EXP];
#pragma unroll
    for (int e = 0; e < N_EXP; e++) acc[e] = 0.0f;

    const float4* xr = (const float4*)(x + (size_t)row * D_MODEL);
#pragma unroll 2
    for (int kk = lane; kk < D_MODEL / 4; kk += 32) {
        float4 xv = __ldg(&xr[kk]);
#pragma unroll
        for (int e = 0; e < N_EXP; e++) {
            float4 q = *(const float4*)(g_qsig + e * D_MODEL + kk * 4);
            acc[e] += xv.x * q.x + xv.y * q.y + xv.z * q.z + xv.w * q.w;
        }
    }
#pragma unroll
    for (int e = 0; e < N_EXP; e++) {
#pragma unroll
        for (int off = 16; off >= 1; off >>= 1)
            acc[e] += __shfl_xor_sync(0xffffffffu, acc[e], off);
    }
    if (lane == 0) {
        int best = 0;
        float bv = acc[0];
#pragma unroll
        for (int e = 1; e < N_EXP; e++)
            if (acc[e] > bv) { bv = acc[e]; best = e; }  // strict > : first max wins
        g_tile[row] = best;
        g_rank[row] = atomicAdd(&g_counts[best], 1);
    }
}

__global__ void offsets_kernel() {
    if (threadIdx.x == 0) {
        int s = 0;
#pragma unroll
        for (int e = 0; e < N_EXP; e++) { g_offsets[e] = s; s += g_counts[e]; }
    }
}

__global__ void scatter_kernel(int B, float* __restrict__ tail) {
    int row = blockIdx.x * blockDim.x + threadIdx.x;
    if (row >= B) return;
    int e = g_tile[row];
    g_perm[g_offsets[e] + g_rank[row]] = row;
    if (tail) tail[row] = (float)e;
}

// ---------------- tf32 mma.sync expert GEMM ----------------
// CTA: 128 gathered rows x 128 cols x K=1024. 8 warps 2x4, warp tile 64x32.
// 3-stage cp.async ring, 1 barrier per chunk, 2 CTAs/SM.
__global__ void __launch_bounds__(256, 2) expert_gemm_mma(
    const float* __restrict__ x, const float* __restrict__ W,
    const float* __restrict__ bias, float* __restrict__ out, int B)
{
    const int e   = blockIdx.z;
    const int cnt = g_counts[e];
    const int m0  = blockIdx.y * BM;
    if (m0 >= cnt) return;                 // empty tile
    const int n0   = blockIdx.x * BN;
    const int base = g_offsets[e];
    const int rem  = cnt - m0;

    extern __shared__ char smem[];
    const uint32_t sb = smem_u32(smem);

    const int tid  = threadIdx.x;
    const int wid  = tid >> 5;
    const int lane = tid & 31;
    const int g    = lane >> 2;            // 0..7
    const int t    = lane & 3;             // 0..3
    const int warp_m = wid >> 2;           // 0..1 (64-row halves)
    const int warp_n = wid & 3;            // 0..3 (32-col quarters)

    // ---- async loader mapping: thread -> (row tid>>1, 64B half-row) for A and B ----
    const int lrow  = tid >> 1;
    const int lsegB = (tid & 1) * 64;
    const int arloc = (lrow < rem) ? lrow : (rem - 1);
    const char* aSrc = (const char*)(x + (size_t)__ldg(&g_perm[base + m0 + arloc]) * D_MODEL) + lsegB;
    const char* bSrc = (const char*)(W + ((size_t)e * D_MODEL + (size_t)(n0 + lrow)) * D_MODEL) + lsegB;
    const uint32_t aDst = sb + (uint32_t)lrow * (KPAD * 4) + lsegB;
    const uint32_t bDst = aDst + A_STG_BYTES;

    // prologue: fill stages 0,1 with chunks 0,1 (one commit each)
#pragma unroll
    for (int c = 0; c < 2; c++) {
        const uint32_t so = (uint32_t)c * STG_BYTES;
        const char* a = aSrc + (size_t)c * 128;
        const char* b = bSrc + (size_t)c * 128;
#pragma unroll
        for (int s = 0; s < 4; s++) {
            cpa16(aDst + so + s * 16, a + s * 16);
            cpa16(bDst + so + s * 16, b + s * 16);
        }
        CP_COMMIT();
    }

    float acc[4][4][4];
#pragma unroll
    for (int i = 0; i < 4; i++)
#pragma unroll
        for (int j = 0; j < 4; j++)
#pragma unroll
            for (int r = 0; r < 4; r++) acc[i][j][r] = 0.0f;

    int stage = 0;
    for (int c = 0; c < NCH; c++) {
        if (c < NCH - 1) asm volatile("cp.async.wait_group 1;" ::: "memory");
        else             asm volatile("cp.async.wait_group 0;" ::: "memory");
        __syncthreads();   // single barrier per chunk

        // prefetch chunk c+2 into stage (c+2)%3 (that stage was last read at iter c-1)
        if (c + 2 < NCH) {
            int fs = stage + 2; if (fs >= NSTG) fs -= NSTG;
            const uint32_t so = (uint32_t)fs * STG_BYTES;
            const char* a = aSrc + (size_t)(c + 2) * 128;
            const char* b = bSrc + (size_t)(c + 2) * 128;
#pragma unroll
            for (int s = 0; s < 4; s++) {
                cpa16(aDst + so + s * 16, a + s * 16);
                cpa16(bDst + so + s * 16, b + s * 16);
            }
            CP_COMMIT();
        }

        const uint32_t* sA = (const uint32_t*)(smem + stage * STG_BYTES) + (warp_m * 64) * KPAD;
        const uint32_t* sB = (const uint32_t*)(smem + stage * STG_BYTES + A_STG_BYTES) + (warp_n * 32) * KPAD;

#pragma unroll
        for (int k0 = 0; k0 < BK; k0 += 8) {
            uint32_t af[4][4], bf[4][2];
#pragma unroll
            for (int mf = 0; mf < 4; mf++) {
                const uint32_t* pr = sA + (mf * 16 + g) * KPAD + k0 + t;
                af[mf][0] = pr[0];
                af[mf][1] = pr[8 * KPAD];
                af[mf][2] = pr[4];
                af[mf][3] = pr[8 * KPAD + 4];
            }
#pragma unroll
            for (int nf = 0; nf < 4; nf++) {
                const uint32_t* pc = sB + (nf * 8 + g) * KPAD + k0 + t;
                bf[nf][0] = pc[0];
                bf[nf][1] = pc[4];
            }
#pragma unroll
            for (int mf = 0; mf < 4; mf++)
#pragma unroll
                for (int nf = 0; nf < 4; nf++)
                    mma_tf32(acc[mf][nf], af[mf], bf[nf]);
        }

        stage++; if (stage >= NSTG) stage -= NSTG;
    }

    // ---- fused epilogue: +bias, relu, +residual, scatter to original rows ----
    const float* bias_e = bias + e * D_MODEL;
    float2 bb[4];
#pragma unroll
    for (int nf = 0; nf < 4; nf++)
        bb[nf] = *(const float2*)(bias_e + n0 + warp_n * 32 + nf * 8 + t * 2);

#pragma unroll
    for (int mf = 0; mf < 4; mf++) {
#pragma unroll
        for (int h = 0; h < 2; h++) {
            const int rloc = warp_m * 64 + mf * 16 + g + h * 8;
            if (rloc >= rem) continue;
            const int gr = __ldg(&g_perm[base + m0 + rloc]);
            const float* xr   = x   + (size_t)gr * D_MODEL;
            float*       orow = out + (size_t)gr * D_MODEL;
#pragma unroll
            for (int nf = 0; nf < 4; nf++) {
                const int col = n0 + warp_n * 32 + nf * 8 + t * 2;
                const float2 xx = __ldg((const float2*)(xr + col));
                float v0 = fmaxf(acc[mf][nf][h * 2 + 0] + bb[nf].x, 0.0f) + xx.x;
                float v1 = fmaxf(acc[mf][nf][h * 2 + 1] + bb[nf].y, 0.0f) + xx.y;
                *(float2*)(orow + col) = make_float2(v0, v1);
            }
        }
    }
}

// ---------------- launch ----------------
extern "C" void kernel_launch(void* const* d_in, const int* in_sizes, int n_in,
                              void* d_out, int out_size) {
    const float* x   = (const float*)d_in[0];
    const float* sig = (const float*)d_in[1];
    const float* W   = (const float*)d_in[2];
    const float* b   = (const float*)d_in[3];
    float* out = (float*)d_out;

    const int B = in_sizes[0] / D_MODEL;

    cudaFuncSetAttribute(expert_gemm_mma,
                         cudaFuncAttributeMaxDynamicSharedMemorySize, SMEM_TOTAL);

    zero_counts_kernel<<<1, 32>>>();
    quantize_sig_kernel<<<(N_EXP * D_MODEL + 255) / 256, 256>>>(sig);
    router_kernel<<<(B + 7) / 8, 256>>>(x, B);
    offsets_kernel<<<1, 32>>>();

    float* tail = nullptr;
    if ((long long)out_size >= (long long)B * D_MODEL + B)
        tail = out + (size_t)B * D_MODEL;
    scatter_kernel<<<(B + 255) / 256, 256>>>(B, tail);

    dim3 grid(D_MODEL / BN, (B + BM - 1) / BM, N_EXP);
    expert_gemm_mma<<<grid, 256, SMEM_TOTAL>>>(x, W, b, out, B);
}

// round 6
// speedup vs baseline: 1.6589x; 1.5435x over previous
#include <cuda_runtime.h>
#include <cuda_fp16.h>
#include <cstdint>

#define D_MODEL 1024
#define N_EXP   16
#define MAX_B   32768
#define THRESH  0.3f

// ---- GEMM tiling (fp16 operands, fp32 accum) ----
#define BM 128
#define BN 128
#define BK 64                               // halfs per k-chunk = 128B per row
#define KPAD_H 72                           // 64 + 8 pad halfs (144B rows, conflict-free)
#define A_STG_BYTES (BM * KPAD_H * 2)       // 18432
#define STG_BYTES   (2 * A_STG_BYTES)       // 36864 (A + B)
#define NSTG 3
#define NCH (D_MODEL / BK)                  // 16 k-chunks
#define SMEM_TOTAL (NSTG * STG_BYTES)       // 110592 -> 2 CTAs/SM

// ---------------- device-global scratch ----------------
__device__ int    g_counts[N_EXP];
__device__ int    g_offsets[N_EXP];
__device__ int    g_tile[MAX_B];
__device__ int    g_rank[MAX_B];
__device__ int    g_perm[MAX_B];
__device__ float  g_qsig[N_EXP * D_MODEL];
__device__ __half g_xh[(size_t)MAX_B * D_MODEL];             // 64 MB fp16 x
__device__ __half g_wh[(size_t)N_EXP * D_MODEL * D_MODEL];   // 32 MB fp16 W

// ---------------- PTX helpers ----------------
__device__ __forceinline__ uint32_t smem_u32(const void* p) {
    uint32_t a;
    asm("{ .reg .u64 t; cvta.to.shared.u64 t, %1; cvt.u32.u64 %0, t; }" : "=r"(a) : "l"(p));
    return a;
}
__device__ __forceinline__ void cpa16(uint32_t dst, const void* src) {
    asm volatile("cp.async.cg.shared.global [%0], [%1], 16;" :: "r"(dst), "l"(src));
}
#define CP_COMMIT() asm volatile("cp.async.commit_group;" ::: "memory")

__device__ __forceinline__ void mma_f16(float* c, const uint32_t* a, const uint32_t* b) {
    asm volatile(
        "mma.sync.aligned.m16n8k16.row.col.f32.f16.f16.f32 "
        "{%0,%1,%2,%3}, {%4,%5,%6,%7}, {%8,%9}, {%0,%1,%2,%3};"
        : "+f"(c[0]), "+f"(c[1]), "+f"(c[2]), "+f"(c[3])
        : "r"(a[0]), "r"(a[1]), "r"(a[2]), "r"(a[3]), "r"(b[0]), "r"(b[1]));
}

// ---------------- tiny setup kernels ----------------
__global__ void zero_counts_kernel() {
    if (threadIdx.x < N_EXP) g_counts[threadIdx.x] = 0;
}

__global__ void quantize_sig_kernel(const float* __restrict__ sig) {
    int i = blockIdx.x * blockDim.x + threadIdx.x;
    if (i < N_EXP * D_MODEL) {
        float s = sig[i];
        g_qsig[i] = (s > THRESH) ? 1.0f : ((s < -THRESH) ? -1.0f : 0.0f);
    }
}

// W fp32 -> fp16
__global__ void convert_w_kernel(const float* __restrict__ W) {
    size_t i = (size_t)(blockIdx.x * blockDim.x + threadIdx.x) * 4;
    if (i < (size_t)N_EXP * D_MODEL * D_MODEL) {
        float4 v = *(const float4*)(W + i);
        half2 h0 = __floats2half2_rn(v.x, v.y);
        half2 h1 = __floats2half2_rn(v.z, v.w);
        *(uint2*)(g_wh + i) = make_uint2(*(uint32_t*)&h0, *(uint32_t*)&h1);
    }
}

// ---------------- router (fused x fp32->fp16 conversion) ----------------
__global__ void router_kernel(const float* __restrict__ x, int B) {
    int tid  = threadIdx.x;
    int warp = tid >> 5;
    int lane = tid & 31;
    int row  = blockIdx.x * 8 + warp;
    if (row >= B) return;

    float acc[N_EXP];
#pragma unroll
    for (int e = 0; e < N_EXP; e++) acc[e] = 0.0f;

    const float4* xr = (const float4*)(x + (size_t)row * D_MODEL);
    __half* xh = g_xh + (size_t)row * D_MODEL;
#pragma unroll 2
    for (int kk = lane; kk < D_MODEL / 4; kk += 32) {
        float4 xv = __ldg(&xr[kk]);
        half2 h0 = __floats2half2_rn(xv.x, xv.y);
        half2 h1 = __floats2half2_rn(xv.z, xv.w);
        *(uint2*)(xh + kk * 4) = make_uint2(*(uint32_t*)&h0, *(uint32_t*)&h1);
#pragma unroll
        for (int e = 0; e < N_EXP; e++) {
            float4 q = *(const float4*)(g_qsig + e * D_MODEL + kk * 4);
            acc[e] += xv.x * q.x + xv.y * q.y + xv.z * q.z + xv.w * q.w;
        }
    }
#pragma unroll
    for (int e = 0; e < N_EXP; e++) {
#pragma unroll
        for (int off = 16; off >= 1; off >>= 1)
            acc[e] += __shfl_xor_sync(0xffffffffu, acc[e], off);
    }
    if (lane == 0) {
        int best = 0;
        float bv = acc[0];
#pragma unroll
        for (int e = 1; e < N_EXP; e++)
            if (acc[e] > bv) { bv = acc[e]; best = e; }  // strict > : first max wins
        g_tile[row] = best;
        g_rank[row] = atomicAdd(&g_counts[best], 1);
    }
}

__global__ void offsets_kernel() {
    if (threadIdx.x == 0) {
        int s = 0;
#pragma unroll
        for (int e = 0; e < N_EXP; e++) { g_offsets[e] = s; s += g_counts[e]; }
    }
}

__global__ void scatter_kernel(int B, float* __restrict__ tail) {
    int row = blockIdx.x * blockDim.x + threadIdx.x;
    if (row >= B) return;
    int e = g_tile[row];
    g_perm[g_offsets[e] + g_rank[row]] = row;
    if (tail) tail[row] = (float)e;
}

// ---------------- fp16 mma.sync expert GEMM ----------------
// CTA: 128 gathered rows x 128 cols x K=1024, fp16 in / fp32 accum.
// 8 warps 2x4, warp tile 64x32, m16n8k16. 3-stage ring, 1 barrier/chunk, 2 CTAs/SM.
__global__ void __launch_bounds__(256, 2) expert_gemm_mma(
    const float* __restrict__ x, const float* __restrict__ bias,
    float* __restrict__ out, int B)
{
    const int e   = blockIdx.z;
    const int cnt = g_counts[e];
    const int m0  = blockIdx.y * BM;
    if (m0 >= cnt) return;                 // empty tile
    const int n0   = blockIdx.x * BN;
    const int base = g_offsets[e];
    const int rem  = cnt - m0;

    extern __shared__ char smem[];
    const uint32_t sb = smem_u32(smem);

    const int tid  = threadIdx.x;
    const int wid  = tid >> 5;
    const int lane = tid & 31;
    const int g    = lane >> 2;            // 0..7
    const int t    = lane & 3;             // 0..3
    const int warp_m = wid >> 2;           // 0..1 (64-row halves)
    const int warp_n = wid & 3;            // 0..3 (32-col quarters)

    // ---- async loader: thread -> (row tid>>1, 64B half-row); chunk = 128B/row ----
    const int lrow  = tid >> 1;
    const int lsegB = (tid & 1) * 64;
    const int arloc = (lrow < rem) ? lrow : (rem - 1);
    const char* aSrc = (const char*)(g_xh + (size_t)__ldg(&g_perm[base + m0 + arloc]) * D_MODEL) + lsegB;
    const char* bSrc = (const char*)(g_wh + ((size_t)e * D_MODEL + (size_t)(n0 + lrow)) * D_MODEL) + lsegB;
    const uint32_t aDst = sb + (uint32_t)lrow * (KPAD_H * 2) + lsegB;
    const uint32_t bDst = aDst + A_STG_BYTES;

    // prologue: stages 0,1 <- chunks 0,1
#pragma unroll
    for (int c = 0; c < 2; c++) {
        const uint32_t so = (uint32_t)c * STG_BYTES;
        const char* a = aSrc + (size_t)c * 128;
        const char* b = bSrc + (size_t)c * 128;
#pragma unroll
        for (int s = 0; s < 4; s++) {
            cpa16(aDst + so + s * 16, a + s * 16);
            cpa16(bDst + so + s * 16, b + s * 16);
        }
        CP_COMMIT();
    }

    float acc[4][4][4];
#pragma unroll
    for (int i = 0; i < 4; i++)
#pragma unroll
        for (int j = 0; j < 4; j++)
#pragma unroll
            for (int r = 0; r < 4; r++) acc[i][j][r] = 0.0f;

    int stage = 0;
    for (int c = 0; c < NCH; c++) {
        if (c < NCH - 1) asm volatile("cp.async.wait_group 1;" ::: "memory");
        else             asm volatile("cp.async.wait_group 0;" ::: "memory");
        __syncthreads();   // single barrier per chunk

        // prefetch chunk c+2 into stage (stage+2)%3
        if (c + 2 < NCH) {
            int fs = stage + 2; if (fs >= NSTG) fs -= NSTG;
            const uint32_t so = (uint32_t)fs * STG_BYTES;
            const char* a = aSrc + (size_t)(c + 2) * 128;
            const char* b = bSrc + (size_t)(c + 2) * 128;
#pragma unroll
            for (int s = 0; s < 4; s++) {
                cpa16(aDst + so + s * 16, a + s * 16);
                cpa16(bDst + so + s * 16, b + s * 16);
            }
            CP_COMMIT();
        }

        const __half* sA = (const __half*)(smem + stage * STG_BYTES) + (warp_m * 64) * KPAD_H;
        const __half* sB = (const __half*)(smem + stage * STG_BYTES + A_STG_BYTES) + (warp_n * 32) * KPAD_H;

#pragma unroll
        for (int k0 = 0; k0 < BK; k0 += 16) {
            uint32_t af[4][4], bf[4][2];
#pragma unroll
            for (int mf = 0; mf < 4; mf++) {
                const __half* r0 = sA + (mf * 16 + g) * KPAD_H + k0 + 2 * t;
                const __half* r1 = r0 + 8 * KPAD_H;
                af[mf][0] = *(const uint32_t*)(r0);
                af[mf][1] = *(const uint32_t*)(r1);
                af[mf][2] = *(const uint32_t*)(r0 + 8);
                af[mf][3] = *(const uint32_t*)(r1 + 8);
            }
#pragma unroll
            for (int nf = 0; nf < 4; nf++) {
                const __half* pc = sB + (nf * 8 + g) * KPAD_H + k0 + 2 * t;
                bf[nf][0] = *(const uint32_t*)(pc);
                bf[nf][1] = *(const uint32_t*)(pc + 8);
            }
#pragma unroll
            for (int mf = 0; mf < 4; mf++)
#pragma unroll
                for (int nf = 0; nf < 4; nf++)
                    mma_f16(acc[mf][nf], af[mf], bf[nf]);
        }

        stage++; if (stage >= NSTG) stage -= NSTG;
    }

    // ---- fused epilogue: +bias, relu, +residual (fp32), scatter to original rows ----
    const float* bias_e = bias + e * D_MODEL;
    float2 bb[4];
#pragma unroll
    for (int nf = 0; nf < 4; nf++)
        bb[nf] = *(const float2*)(bias_e + n0 + warp_n * 32 + nf * 8 + t * 2);

#pragma unroll
    for (int mf = 0; mf < 4; mf++) {
#pragma unroll
        for (int h = 0; h < 2; h++) {
            const int rloc = warp_m * 64 + mf * 16 + g + h * 8;
            if (rloc >= rem) continue;
            const int gr = __ldg(&g_perm[base + m0 + rloc]);
            const float* xr   = x   + (size_t)gr * D_MODEL;
            float*       orow = out + (size_t)gr * D_MODEL;
#pragma unroll
            for (int nf = 0; nf < 4; nf++) {
                const int col = n0 + warp_n * 32 + nf * 8 + t * 2;
                const float2 xx = __ldg((const float2*)(xr + col));
                float v0 = fmaxf(acc[mf][nf][h * 2 + 0] + bb[nf].x, 0.0f) + xx.x;
                float v1 = fmaxf(acc[mf][nf][h * 2 + 1] + bb[nf].y, 0.0f) + xx.y;
                *(float2*)(orow + col) = make_float2(v0, v1);
            }
        }
    }
}

// ---------------- launch ----------------
extern "C" void kernel_launch(void* const* d_in, const int* in_sizes, int n_in,
                              void* d_out, int out_size) {
    const float* x   = (const float*)d_in[0];
    const float* sig = (const float*)d_in[1];
    const float* W   = (const float*)d_in[2];
    const float* b   = (const float*)d_in[3];
    float* out = (float*)d_out;

    const int B = in_sizes[0] / D_MODEL;

    cudaFuncSetAttribute(expert_gemm_mma,
                         cudaFuncAttributeMaxDynamicSharedMemorySize, SMEM_TOTAL);

    zero_counts_kernel<<<1, 32>>>();
    quantize_sig_kernel<<<(N_EXP * D_MODEL + 255) / 256, 256>>>(sig);
    convert_w_kernel<<<(N_EXP * D_MODEL * D_MODEL / 4 + 255) / 256, 256>>>(W);
    router_kernel<<<(B + 7) / 8, 256>>>(x, B);
    offsets_kernel<<<1, 32>>>();

    float* tail = nullptr;
    if ((long long)out_size >= (long long)B * D_MODEL + B)
        tail = out + (size_t)B * D_MODEL;
    scatter_kernel<<<(B + 255) / 256, 256>>>(B, tail);

    dim3 grid(D_MODEL / BN, (B + BM - 1) / BM, N_EXP);
    expert_gemm_mma<<<grid, 256, SMEM_TOTAL>>>(x, b, out, B);
}

// round 7
// speedup vs baseline: 1.7728x; 1.0687x over previous
#include <cuda_runtime.h>
#include <cuda_fp16.h>
#include <cstdint>

#define D_MODEL 1024
#define N_EXP   16
#define MAX_B   32768
#define THRESH  0.3f

// ---- GEMM tiling (fp16 operands, fp32 accum) ----
#define BM 128
#define BN 128
#define BK 64                               // halfs per k-chunk = 128B per row
#define KPAD_H 72                           // 64 + 8 pad halfs (144B rows, conflict-free)
#define A_STG_BYTES (BM * KPAD_H * 2)       // 18432
#define STG_BYTES   (2 * A_STG_BYTES)       // 36864 (A + B)
#define NSTG 3
#define NCH (D_MODEL / BK)                  // 16 k-chunks
#define SMEM_TOTAL (NSTG * STG_BYTES)       // 110592 -> 2 CTAs/SM

// ---------------- device-global scratch ----------------
__device__ int    g_counts[N_EXP];
__device__ int    g_offsets[N_EXP];
__device__ int    g_tile[MAX_B];
__device__ int    g_rank[MAX_B];
__device__ int    g_perm[MAX_B];
__device__ float  g_qsig[N_EXP * D_MODEL];
__device__ __half g_xh[(size_t)MAX_B * D_MODEL];             // 64 MB fp16 x
__device__ __half g_wh[(size_t)N_EXP * D_MODEL * D_MODEL];   // 32 MB fp16 W

// ---------------- PTX helpers ----------------
__device__ __forceinline__ uint32_t smem_u32(const void* p) {
    uint32_t a;
    asm("{ .reg .u64 t; cvta.to.shared.u64 t, %1; cvt.u32.u64 %0, t; }" : "=r"(a) : "l"(p));
    return a;
}
__device__ __forceinline__ void cpa16(uint32_t dst, const void* src) {
    asm volatile("cp.async.cg.shared.global [%0], [%1], 16;" :: "r"(dst), "l"(src));
}
#define CP_COMMIT() asm volatile("cp.async.commit_group;" ::: "memory")

__device__ __forceinline__ void mma_f16(float* c, const uint32_t* a, const uint32_t* b) {
    asm volatile(
        "mma.sync.aligned.m16n8k16.row.col.f32.f16.f16.f32 "
        "{%0,%1,%2,%3}, {%4,%5,%6,%7}, {%8,%9}, {%0,%1,%2,%3};"
        : "+f"(c[0]), "+f"(c[1]), "+f"(c[2]), "+f"(c[3])
        : "r"(a[0]), "r"(a[1]), "r"(a[2]), "r"(a[3]), "r"(b[0]), "r"(b[1]));
}
__device__ __forceinline__ void ldsm_x4(uint32_t* r, uint32_t addr) {
    asm volatile("ldmatrix.sync.aligned.m8n8.x4.shared.b16 {%0,%1,%2,%3}, [%4];"
                 : "=r"(r[0]), "=r"(r[1]), "=r"(r[2]), "=r"(r[3]) : "r"(addr));
}
__device__ __forceinline__ void ldsm_x2(uint32_t* r, uint32_t addr) {
    asm volatile("ldmatrix.sync.aligned.m8n8.x2.shared.b16 {%0,%1}, [%2];"
                 : "=r"(r[0]), "=r"(r[1]) : "r"(addr));
}

// ---------------- setup: zero counts + quantize signatures (merged) ----------------
__global__ void setup_kernel(const float* __restrict__ sig) {
    int i = blockIdx.x * blockDim.x + threadIdx.x;
    if (i < N_EXP) g_counts[i] = 0;
    if (i < N_EXP * D_MODEL) {
        float s = sig[i];
        g_qsig[i] = (s > THRESH) ? 1.0f : ((s < -THRESH) ? -1.0f : 0.0f);
    }
}

// W fp32 -> fp16
__global__ void convert_w_kernel(const float* __restrict__ W) {
    size_t i = (size_t)(blockIdx.x * blockDim.x + threadIdx.x) * 4;
    if (i < (size_t)N_EXP * D_MODEL * D_MODEL) {
        float4 v = *(const float4*)(W + i);
        half2 h0 = __floats2half2_rn(v.x, v.y);
        half2 h1 = __floats2half2_rn(v.z, v.w);
        *(uint2*)(g_wh + i) = make_uint2(*(uint32_t*)&h0, *(uint32_t*)&h1);
    }
}

// ---------------- router: 4 rows per warp (qsig L1 traffic /4), fused x->fp16 ----
__global__ void router_kernel(const float* __restrict__ x, int B) {
    const int tid  = threadIdx.x;
    const int warp = tid >> 5;
    const int lane = tid & 31;
    const int row0 = blockIdx.x * 32 + warp * 4;
    if (row0 >= B) return;

    float acc[4][N_EXP];
#pragma unroll
    for (int r = 0; r < 4; r++)
#pragma unroll
        for (int e = 0; e < N_EXP; e++) acc[r][e] = 0.0f;

    const float4* xr[4];
    __half* xh[4];
#pragma unroll
    for (int r = 0; r < 4; r++) {
        int row = row0 + r < B ? row0 + r : B - 1;
        xr[r] = (const float4*)(x + (size_t)row * D_MODEL);
        xh[r] = g_xh + (size_t)row * D_MODEL;
    }

    for (int kk = lane; kk < D_MODEL / 4; kk += 32) {
        float4 xv[4];
#pragma unroll
        for (int r = 0; r < 4; r++) {
            xv[r] = __ldg(&xr[r][kk]);
            half2 h0 = __floats2half2_rn(xv[r].x, xv[r].y);
            half2 h1 = __floats2half2_rn(xv[r].z, xv[r].w);
            *(uint2*)(xh[r] + kk * 4) = make_uint2(*(uint32_t*)&h0, *(uint32_t*)&h1);
        }
#pragma unroll
        for (int e = 0; e < N_EXP; e++) {
            float4 q = *(const float4*)(g_qsig + e * D_MODEL + kk * 4);
#pragma unroll
            for (int r = 0; r < 4; r++)
                acc[r][e] += xv[r].x * q.x + xv[r].y * q.y + xv[r].z * q.z + xv[r].w * q.w;
        }
    }

#pragma unroll
    for (int r = 0; r < 4; r++) {
#pragma unroll
        for (int e = 0; e < N_EXP; e++) {
#pragma unroll
            for (int off = 16; off >= 1; off >>= 1)
                acc[r][e] += __shfl_xor_sync(0xffffffffu, acc[r][e], off);
        }
        if (lane == 0 && row0 + r < B) {
            int best = 0;
            float bv = acc[r][0];
#pragma unroll
            for (int e = 1; e < N_EXP; e++)
                if (acc[r][e] > bv) { bv = acc[r][e]; best = e; }  // first max wins
            g_tile[row0 + r] = best;
            g_rank[row0 + r] = atomicAdd(&g_counts[best], 1);
        }
    }
}

__global__ void offsets_kernel() {
    if (threadIdx.x == 0) {
        int s = 0;
#pragma unroll
        for (int e = 0; e < N_EXP; e++) { g_offsets[e] = s; s += g_counts[e]; }
    }
}

__global__ void scatter_kernel(int B, float* __restrict__ tail) {
    int row = blockIdx.x * blockDim.x + threadIdx.x;
    if (row >= B) return;
    int e = g_tile[row];
    g_perm[g_offsets[e] + g_rank[row]] = row;
    if (tail) tail[row] = (float)e;
}

// ---------------- fp16 mma.sync expert GEMM (ldmatrix fragments) ----------------
// CTA: 128 gathered rows x 128 cols x K=1024, 8 warps 2x4, warp tile 64x32.
__global__ void __launch_bounds__(256, 2) expert_gemm_mma(
    const float* __restrict__ x, const float* __restrict__ bias,
    float* __restrict__ out, int B)
{
    const int e   = blockIdx.z;
    const int cnt = g_counts[e];
    const int m0  = blockIdx.y * BM;
    if (m0 >= cnt) return;                 // empty tile
    const int n0   = blockIdx.x * BN;
    const int base = g_offsets[e];
    const int rem  = cnt - m0;

    extern __shared__ char smem[];
    const uint32_t sb = smem_u32(smem);

    const int tid  = threadIdx.x;
    const int wid  = tid >> 5;
    const int lane = tid & 31;
    const int g    = lane >> 2;            // 0..7
    const int t    = lane & 3;             // 0..3
    const int warp_m = wid >> 2;           // 0..1 (64-row halves)
    const int warp_n = wid & 3;            // 0..3 (32-col quarters)

    // ---- async loader: thread -> (row tid>>1, 64B half-row); chunk = 128B/row ----
    const int lrow  = tid >> 1;
    const int lsegB = (tid & 1) * 64;
    const int arloc = (lrow < rem) ? lrow : (rem - 1);
    const char* aSrc = (const char*)(g_xh + (size_t)__ldg(&g_perm[base + m0 + arloc]) * D_MODEL) + lsegB;
    const char* bSrc = (const char*)(g_wh + ((size_t)e * D_MODEL + (size_t)(n0 + lrow)) * D_MODEL) + lsegB;
    const uint32_t aDst = sb + (uint32_t)lrow * (KPAD_H * 2) + lsegB;
    const uint32_t bDst = aDst + A_STG_BYTES;

    // ---- ldmatrix per-lane offsets (halfs, within stage) ----
    // A x4: lanes 0-7 rows+0 @k0, 8-15 rows+8 @k0, 16-23 rows+0 @k0+8, 24-31 rows+8 @k0+8
    const int q8 = lane >> 3;              // 0..3 matrix index
    const int r8 = lane & 7;
    const uint32_t aoffH = (uint32_t)((warp_m * 64 + (q8 & 1) * 8 + r8) * KPAD_H + (q8 >> 1) * 8);
    // B x2: lanes 0-7 rows n @k0, lanes 8-15 rows n @k0+8 (lanes>=16 ignored)
    const uint32_t boffH = (uint32_t)((warp_n * 32 + r8) * KPAD_H + ((lane >> 3) & 1) * 8);

    // prologue: stages 0,1 <- chunks 0,1
#pragma unroll
    for (int c = 0; c < 2; c++) {
        const uint32_t so = (uint32_t)c * STG_BYTES;
        const char* a = aSrc + (size_t)c * 128;
        const char* b = bSrc + (size_t)c * 128;
#pragma unroll
        for (int s = 0; s < 4; s++) {
            cpa16(aDst + so + s * 16, a + s * 16);
            cpa16(bDst + so + s * 16, b + s * 16);
        }
        CP_COMMIT();
    }

    float acc[4][4][4];
#pragma unroll
    for (int i = 0; i < 4; i++)
#pragma unroll
        for (int j = 0; j < 4; j++)
#pragma unroll
            for (int r = 0; r < 4; r++) acc[i][j][r] = 0.0f;

    int stage = 0;
    for (int c = 0; c < NCH; c++) {
        if (c < NCH - 1) asm volatile("cp.async.wait_group 1;" ::: "memory");
        else             asm volatile("cp.async.wait_group 0;" ::: "memory");
        __syncthreads();   // single barrier per chunk

        // prefetch chunk c+2 into stage (stage+2)%3
        if (c + 2 < NCH) {
            int fs = stage + 2; if (fs >= NSTG) fs -= NSTG;
            const uint32_t so = (uint32_t)fs * STG_BYTES;
            const char* a = aSrc + (size_t)(c + 2) * 128;
            const char* b = bSrc + (size_t)(c + 2) * 128;
#pragma unroll
            for (int s = 0; s < 4; s++) {
                cpa16(aDst + so + s * 16, a + s * 16);
                cpa16(bDst + so + s * 16, b + s * 16);
            }
            CP_COMMIT();
        }

        const uint32_t sA = sb + stage * STG_BYTES;
        const uint32_t sB = sA + A_STG_BYTES;

#pragma unroll
        for (int k0 = 0; k0 < BK; k0 += 16) {
            uint32_t af[4][4], bf[4][2];
#pragma unroll
            for (int mf = 0; mf < 4; mf++)
                ldsm_x4(af[mf], sA + (aoffH + (uint32_t)(mf * 16) * KPAD_H + k0) * 2);
#pragma unroll
            for (int nf = 0; nf < 4; nf++)
                ldsm_x2(bf[nf], sB + (boffH + (uint32_t)(nf * 8) * KPAD_H + k0) * 2);
#pragma unroll
            for (int mf = 0; mf < 4; mf++)
#pragma unroll
                for (int nf = 0; nf < 4; nf++)
                    mma_f16(acc[mf][nf], af[mf], bf[nf]);
        }

        stage++; if (stage >= NSTG) stage -= NSTG;
    }

    // ---- fused epilogue: +bias, relu, +residual (fp32), scatter to original rows ----
    const float* bias_e = bias + e * D_MODEL;
    float2 bb[4];
#pragma unroll
    for (int nf = 0; nf < 4; nf++)
        bb[nf] = *(const float2*)(bias_e + n0 + warp_n * 32 + nf * 8 + t * 2);

#pragma unroll
    for (int mf = 0; mf < 4; mf++) {
#pragma unroll
        for (int h = 0; h < 2; h++) {
            const int rloc = warp_m * 64 + mf * 16 + g + h * 8;
            if (rloc >= rem) continue;
            const int gr = __ldg(&g_perm[base + m0 + rloc]);
            const float* xr   = x   + (size_t)gr * D_MODEL;
            float*       orow = out + (size_t)gr * D_MODEL;
#pragma unroll
            for (int nf = 0; nf < 4; nf++) {
                const int col = n0 + warp_n * 32 + nf * 8 + t * 2;
                const float2 xx = __ldg((const float2*)(xr + col));
                float v0 = fmaxf(acc[mf][nf][h * 2 + 0] + bb[nf].x, 0.0f) + xx.x;
                float v1 = fmaxf(acc[mf][nf][h * 2 + 1] + bb[nf].y, 0.0f) + xx.y;
                *(float2*)(orow + col) = make_float2(v0, v1);
            }
        }
    }
}

// ---------------- launch ----------------
extern "C" void kernel_launch(void* const* d_in, const int* in_sizes, int n_in,
                              void* d_out, int out_size) {
    const float* x   = (const float*)d_in[0];
    const float* sig = (const float*)d_in[1];
    const float* W   = (const float*)d_in[2];
    const float* b   = (const float*)d_in[3];
    float* out = (float*)d_out;

    const int B = in_sizes[0] / D_MODEL;

    cudaFuncSetAttribute(expert_gemm_mma,
                         cudaFuncAttributeMaxDynamicSharedMemorySize, SMEM_TOTAL);

    setup_kernel<<<(N_EXP * D_MODEL + 255) / 256, 256>>>(sig);
    convert_w_kernel<<<(N_EXP * D_MODEL * D_MODEL / 4 + 255) / 256, 256>>>(W);
    router_kernel<<<(B + 31) / 32, 256>>>(x, B);
    offsets_kernel<<<1, 32>>>();

    float* tail = nullptr;
    if ((long long)out_size >= (long long)B * D_MODEL + B)
        tail = out + (size_t)B * D_MODEL;
    scatter_kernel<<<(B + 255) / 256, 256>>>(B, tail);

    dim3 grid(D_MODEL / BN, (B + BM - 1) / BM, N_EXP);
    expert_gemm_mma<<<grid, 256, SMEM_TOTAL>>>(x, b, out, B);
}

// round 8
// speedup vs baseline: 1.8499x; 1.0435x over previous
#include <cuda_runtime.h>
#include <cuda_fp16.h>
#include <cstdint>

#define D_MODEL 1024
#define N_EXP   16
#define MAX_B   32768
#define THRESH  0.3f

// ---- GEMM tiling (fp16 operands, fp32 accum) ----
#define BM 128
#define BN 128
#define BK 64                               // halfs per k-chunk = 128B per row
#define KPAD_H 72                           // 64 + 8 pad halfs (144B rows, conflict-free)
#define A_STG_BYTES (BM * KPAD_H * 2)       // 18432
#define STG_BYTES   (2 * A_STG_BYTES)       // 36864 (A + B)
#define NSTG 3
#define NCH (D_MODEL / BK)                  // 16 k-chunks
#define SMEM_TOTAL (NSTG * STG_BYTES)       // 110592 -> 2 CTAs/SM
#define NTILES_MAX (MAX_B / BM + N_EXP)     // 272: sum of ceil(cnt/BM) upper bound

// ---------------- device-global scratch ----------------
__device__ int    g_counts[N_EXP];
__device__ int    g_offsets[N_EXP];
__device__ int    g_tstart[N_EXP + 1];       // per-expert m-tile prefix
__device__ int    g_ntiles;
__device__ int    g_tile[MAX_B];
__device__ int    g_rank[MAX_B];
__device__ int    g_perm[MAX_B];
__device__ float  g_qsig[N_EXP * D_MODEL];
__device__ __half g_xh[(size_t)MAX_B * D_MODEL];             // 64 MB fp16 x
__device__ __half g_wh[(size_t)N_EXP * D_MODEL * D_MODEL];   // 32 MB fp16 W

// ---------------- PTX helpers ----------------
__device__ __forceinline__ uint32_t smem_u32(const void* p) {
    uint32_t a;
    asm("{ .reg .u64 t; cvta.to.shared.u64 t, %1; cvt.u32.u64 %0, t; }" : "=r"(a) : "l"(p));
    return a;
}
__device__ __forceinline__ void cpa16(uint32_t dst, const void* src) {
    asm volatile("cp.async.cg.shared.global [%0], [%1], 16;" :: "r"(dst), "l"(src));
}
#define CP_COMMIT() asm volatile("cp.async.commit_group;" ::: "memory")

__device__ __forceinline__ void mma_f16(float* c, const uint32_t* a, const uint32_t* b) {
    asm volatile(
        "mma.sync.aligned.m16n8k16.row.col.f32.f16.f16.f32 "
        "{%0,%1,%2,%3}, {%4,%5,%6,%7}, {%8,%9}, {%0,%1,%2,%3};"
        : "+f"(c[0]), "+f"(c[1]), "+f"(c[2]), "+f"(c[3])
        : "r"(a[0]), "r"(a[1]), "r"(a[2]), "r"(a[3]), "r"(b[0]), "r"(b[1]));
}
__device__ __forceinline__ void ldsm_x4(uint32_t* r, uint32_t addr) {
    asm volatile("ldmatrix.sync.aligned.m8n8.x4.shared.b16 {%0,%1,%2,%3}, [%4];"
                 : "=r"(r[0]), "=r"(r[1]), "=r"(r[2]), "=r"(r[3]) : "r"(addr));
}

// ---------------- convert W fp32->fp16 + zero counts + quantize sigs ----------------
__global__ void convert_w_kernel(const float* __restrict__ W, const float* __restrict__ sig) {
    int gi = blockIdx.x * blockDim.x + threadIdx.x;
    if (gi < N_EXP) g_counts[gi] = 0;
    if (gi < N_EXP * D_MODEL) {
        float s = sig[gi];
        g_qsig[gi] = (s > THRESH) ? 1.0f : ((s < -THRESH) ? -1.0f : 0.0f);
    }
    size_t i = (size_t)gi * 4;
    if (i < (size_t)N_EXP * D_MODEL * D_MODEL) {
        float4 v = *(const float4*)(W + i);
        half2 h0 = __floats2half2_rn(v.x, v.y);
        half2 h1 = __floats2half2_rn(v.z, v.w);
        *(uint2*)(g_wh + i) = make_uint2(*(uint32_t*)&h0, *(uint32_t*)&h1);
    }
}

// ---------------- router: 4 rows per warp, fused x->fp16 ----------------
__global__ void router_kernel(const float* __restrict__ x, int B) {
    const int tid  = threadIdx.x;
    const int warp = tid >> 5;
    const int lane = tid & 31;
    const int row0 = blockIdx.x * 32 + warp * 4;
    if (row0 >= B) return;

    float acc[4][N_EXP];
#pragma unroll
    for (int r = 0; r < 4; r++)
#pragma unroll
        for (int e = 0; e < N_EXP; e++) acc[r][e] = 0.0f;

    const float4* xr[4];
    __half* xh[4];
#pragma unroll
    for (int r = 0; r < 4; r++) {
        int row = row0 + r < B ? row0 + r : B - 1;
        xr[r] = (const float4*)(x + (size_t)row * D_MODEL);
        xh[r] = g_xh + (size_t)row * D_MODEL;
    }

    for (int kk = lane; kk < D_MODEL / 4; kk += 32) {
        float4 xv[4];
#pragma unroll
        for (int r = 0; r < 4; r++) {
            xv[r] = __ldg(&xr[r][kk]);
            half2 h0 = __floats2half2_rn(xv[r].x, xv[r].y);
            half2 h1 = __floats2half2_rn(xv[r].z, xv[r].w);
            *(uint2*)(xh[r] + kk * 4) = make_uint2(*(uint32_t*)&h0, *(uint32_t*)&h1);
        }
#pragma unroll
        for (int e = 0; e < N_EXP; e++) {
            float4 q = *(const float4*)(g_qsig + e * D_MODEL + kk * 4);
#pragma unroll
            for (int r = 0; r < 4; r++)
                acc[r][e] += xv[r].x * q.x + xv[r].y * q.y + xv[r].z * q.z + xv[r].w * q.w;
        }
    }

#pragma unroll
    for (int r = 0; r < 4; r++) {
#pragma unroll
        for (int e = 0; e < N_EXP; e++) {
#pragma unroll
            for (int off = 16; off >= 1; off >>= 1)
                acc[r][e] += __shfl_xor_sync(0xffffffffu, acc[r][e], off);
        }
        if (lane == 0 && row0 + r < B) {
            int best = 0;
            float bv = acc[r][0];
#pragma unroll
            for (int e = 1; e < N_EXP; e++)
                if (acc[r][e] > bv) { bv = acc[r][e]; best = e; }  // first max wins
            g_tile[row0 + r] = best;
            g_rank[row0 + r] = atomicAdd(&g_counts[best], 1);
        }
    }
}

__global__ void offsets_kernel() {
    if (threadIdx.x == 0) {
        int s = 0, ts = 0;
#pragma unroll
        for (int e = 0; e < N_EXP; e++) {
            g_offsets[e] = s;
            g_tstart[e]  = ts;
            s  += g_counts[e];
            ts += (g_counts[e] + BM - 1) / BM;
        }
        g_tstart[N_EXP] = ts;
        g_ntiles = ts;
    }
}

__global__ void scatter_kernel(int B, float* __restrict__ tail) {
    int row = blockIdx.x * blockDim.x + threadIdx.x;
    if (row >= B) return;
    int e = g_tile[row];
    g_perm[g_offsets[e] + g_rank[row]] = row;
    if (tail) tail[row] = (float)e;
}

// ---------------- fp16 mma.sync expert GEMM (flat tile scheduler) ----------------
// grid = (NTILES_MAX, 8): x = flat m-tile, y = n-tile. 8 warps 2x4, warp tile 64x32.
__global__ void __launch_bounds__(256, 2) expert_gemm_mma(
    const float* __restrict__ x, const float* __restrict__ bias,
    float* __restrict__ out, int B)
{
    const int bx = blockIdx.x;
    if (bx >= g_ntiles) return;
    int e = 0;
#pragma unroll
    for (int i = 1; i < N_EXP; i++)
        if (g_tstart[i] <= bx) e = i;
    const int cnt = g_counts[e];
    const int m0  = (bx - g_tstart[e]) * BM;
    const int n0   = blockIdx.y * BN;
    const int base = g_offsets[e];
    const int rem  = cnt - m0;

    extern __shared__ char smem[];
    const uint32_t sb = smem_u32(smem);

    const int tid  = threadIdx.x;
    const int wid  = tid >> 5;
    const int lane = tid & 31;
    const int g    = lane >> 2;            // 0..7
    const int t    = lane & 3;             // 0..3
    const int warp_m = wid >> 2;           // 0..1 (64-row halves)
    const int warp_n = wid & 3;            // 0..3 (32-col quarters)

    // ---- async loader: thread -> (row tid>>1, 64B half-row); chunk = 128B/row ----
    const int lrow  = tid >> 1;
    const int lsegB = (tid & 1) * 64;
    const int arloc = (lrow < rem) ? lrow : (rem - 1);
    const char* aSrc = (const char*)(g_xh + (size_t)__ldg(&g_perm[base + m0 + arloc]) * D_MODEL) + lsegB;
    const char* bSrc = (const char*)(g_wh + ((size_t)e * D_MODEL + (size_t)(n0 + lrow)) * D_MODEL) + lsegB;
    const uint32_t aDst = sb + (uint32_t)lrow * (KPAD_H * 2) + lsegB;
    const uint32_t bDst = aDst + A_STG_BYTES;

    // ---- ldmatrix per-lane offsets (halfs, within stage) ----
    const int q8 = lane >> 3;              // 0..3 matrix index
    const int r8 = lane & 7;
    // A x4: m0/m1 = rows +0/+8 @k0, m2/m3 = rows +0/+8 @k0+8
    const uint32_t aoffH = (uint32_t)((warp_m * 64 + (q8 & 1) * 8 + r8) * KPAD_H + (q8 >> 1) * 8);
    // B x4 pair: m0/m1 = col-group p rows r8 @k0/k0+8, m2/m3 = col-group p+1
    const uint32_t boffH = (uint32_t)((warp_n * 32 + (q8 >> 1) * 8 + r8) * KPAD_H + (q8 & 1) * 8);

    // prologue: stages 0,1 <- chunks 0,1
#pragma unroll
    for (int c = 0; c < 2; c++) {
        const uint32_t so = (uint32_t)c * STG_BYTES;
        const char* a = aSrc + (size_t)c * 128;
        const char* b = bSrc + (size_t)c * 128;
#pragma unroll
        for (int s = 0; s < 4; s++) {
            cpa16(aDst + so + s * 16, a + s * 16);
            cpa16(bDst + so + s * 16, b + s * 16);
        }
        CP_COMMIT();
    }

    float acc[4][4][4];
#pragma unroll
    for (int i = 0; i < 4; i++)
#pragma unroll
        for (int j = 0; j < 4; j++)
#pragma unroll
            for (int r = 0; r < 4; r++) acc[i][j][r] = 0.0f;

    int stage = 0;
    for (int c = 0; c < NCH; c++) {
        if (c < NCH - 1) asm volatile("cp.async.wait_group 1;" ::: "memory");
        else             asm volatile("cp.async.wait_group 0;" ::: "memory");
        __syncthreads();   // single barrier per chunk

        // prefetch chunk c+2 into stage (stage+2)%3
        if (c + 2 < NCH) {
            int fs = stage + 2; if (fs >= NSTG) fs -= NSTG;
            const uint32_t so = (uint32_t)fs * STG_BYTES;
            const char* a = aSrc + (size_t)(c + 2) * 128;
            const char* b = bSrc + (size_t)(c + 2) * 128;
#pragma unroll
            for (int s = 0; s < 4; s++) {
                cpa16(aDst + so + s * 16, a + s * 16);
                cpa16(bDst + so + s * 16, b + s * 16);
            }
            CP_COMMIT();
        }

        const uint32_t sA = sb + stage * STG_BYTES;
        const uint32_t sB = sA + A_STG_BYTES;

#pragma unroll
        for (int k0 = 0; k0 < BK; k0 += 16) {
            uint32_t af[4][4], bf[4][2];
#pragma unroll
            for (int mf = 0; mf < 4; mf++)
                ldsm_x4(af[mf], sA + (aoffH + (uint32_t)(mf * 16) * KPAD_H + k0) * 2);
#pragma unroll
            for (int p = 0; p < 2; p++) {
                uint32_t bq[4];
                ldsm_x4(bq, sB + (boffH + (uint32_t)(p * 16) * KPAD_H + k0) * 2);
                bf[p * 2 + 0][0] = bq[0]; bf[p * 2 + 0][1] = bq[1];
                bf[p * 2 + 1][0] = bq[2]; bf[p * 2 + 1][1] = bq[3];
            }
#pragma unroll
            for (int mf = 0; mf < 4; mf++)
#pragma unroll
                for (int nf = 0; nf < 4; nf++)
                    mma_f16(acc[mf][nf], af[mf], bf[nf]);
        }

        stage++; if (stage >= NSTG) stage -= NSTG;
    }

    // ---- fused epilogue: +bias, relu, +residual (fp32), scatter to original rows ----
    const float* bias_e = bias + e * D_MODEL;
    float2 bb[4];
#pragma unroll
    for (int nf = 0; nf < 4; nf++)
        bb[nf] = *(const float2*)(bias_e + n0 + warp_n * 32 + nf * 8 + t * 2);

#pragma unroll
    for (int mf = 0; mf < 4; mf++) {
#pragma unroll
        for (int h = 0; h < 2; h++) {
            const int rloc = warp_m * 64 + mf * 16 + g + h * 8;
            if (rloc >= rem) continue;
            const int gr = __ldg(&g_perm[base + m0 + rloc]);
            const float* xr   = x   + (size_t)gr * D_MODEL;
            float*       orow = out + (size_t)gr * D_MODEL;
#pragma unroll
            for (int nf = 0; nf < 4; nf++) {
                const int col = n0 + warp_n * 32 + nf * 8 + t * 2;
                const float2 xx = __ldg((const float2*)(xr + col));
                float v0 = fmaxf(acc[mf][nf][h * 2 + 0] + bb[nf].x, 0.0f) + xx.x;
                float v1 = fmaxf(acc[mf][nf][h * 2 + 1] + bb[nf].y, 0.0f) + xx.y;
                *(float2*)(orow + col) = make_float2(v0, v1);
            }
        }
    }
}

// ---------------- launch ----------------
extern "C" void kernel_launch(void* const* d_in, const int* in_sizes, int n_in,
                              void* d_out, int out_size) {
    const float* x   = (const float*)d_in[0];
    const float* sig = (const float*)d_in[1];
    const float* W   = (const float*)d_in[2];
    const float* b   = (const float*)d_in[3];
    float* out = (float*)d_out;

    const int B = in_sizes[0] / D_MODEL;

    cudaFuncSetAttribute(expert_gemm_mma,
                         cudaFuncAttributeMaxDynamicSharedMemorySize, SMEM_TOTAL);

    convert_w_kernel<<<(N_EXP * D_MODEL * D_MODEL / 4 + 255) / 256, 256>>>(W, sig);
    router_kernel<<<(B + 31) / 32, 256>>>(x, B);
    offsets_kernel<<<1, 32>>>();

    float* tail = nullptr;
    if ((long long)out_size >= (long long)B * D_MODEL + B)
        tail = out + (size_t)B * D_MODEL;
    scatter_kernel<<<(B + 255) / 256, 256>>>(B, tail);

    dim3 grid(NTILES_MAX, D_MODEL / BN);
    expert_gemm_mma<<<grid, 256, SMEM_TOTAL>>>(x, b, out, B);
}